// round 14
// baseline (speedup 1.0000x reference)
#include <cuda_runtime.h>
#include <math.h>
#include <stdint.h>

#define T_TOK   4096
#define H_DIM   1024
#define N_HEAD  16
#define HEAD_D  64
#define SEQ     1024
#define BATCH   4
#define F_DIM   4096
#define N_EXP   8
#define N_SLOTS (T_TOK * 2)

#define BM 128
#define BN 128
#define BK 16
#define ASTR 20
#define BSTR 136

// ---------------- scratch ----------------
__device__ float g_xn[T_TOK * H_DIM];
__device__ float g_q[T_TOK * H_DIM];
__device__ float g_k[T_TOK * H_DIM];
__device__ float g_v[T_TOK * H_DIM];
__device__ float g_ao[T_TOK * H_DIM];
__device__ float g_x1[T_TOK * H_DIM];
__device__ float g_h1[(size_t)N_SLOTS * F_DIM];
__device__ float g_zero[F_DIM];
__device__ int   g_cnt[N_EXP];
__device__ int   g_fill[N_EXP];
__device__ int   g_off[N_EXP];
__device__ float g_psum[N_EXP];
__device__ int   g_topi[T_TOK * 2];
__device__ float g_topw[T_TOK * 2];
__device__ int   g_slot_tok[N_SLOTS];
__device__ float g_slot_w[N_SLOTS];

// ---------------- helpers ----------------
__device__ __forceinline__ float gelu_tanh(float x) {
    float x3 = x * x * x;
    return 0.5f * x * (1.0f + tanhf(0.7978845608028654f * (x + 0.044715f * x3)));
}

__device__ __forceinline__ void mma_tf32(float (&c)[4], const uint32_t (&a)[4],
                                         const uint32_t (&b)[2]) {
    asm volatile(
        "mma.sync.aligned.m16n8k8.row.col.f32.tf32.tf32.f32 "
        "{%0,%1,%2,%3}, {%4,%5,%6,%7}, {%8,%9}, {%0,%1,%2,%3};"
        : "+f"(c[0]), "+f"(c[1]), "+f"(c[2]), "+f"(c[3])
        : "r"(a[0]), "r"(a[1]), "r"(a[2]), "r"(a[3]), "r"(b[0]), "r"(b[1]));
}

__device__ __forceinline__ void cp16(uint32_t dst, const void* src) {
    asm volatile("cp.async.cg.shared.global [%0], [%1], 16;"
                 :: "r"(dst), "l"(src));
}
__device__ __forceinline__ void cp_commit() { asm volatile("cp.async.commit_group;"); }
__device__ __forceinline__ void cp_wait0()  { asm volatile("cp.async.wait_group 0;"); }

// CTA swizzle: launch order (x fastest) -> G-row x all-col patches.
// REQUIRES G | gridDim.y. Returns (rowb, colb).
__device__ __forceinline__ void swizzle_rc(int G, int& rowb, int& colb) {
    int lin = blockIdx.y * gridDim.x + blockIdx.x;
    int per = G * gridDim.x;
    int grp = lin / per, rem = lin % per;
    colb = rem / G;
    rowb = grp * G + rem % G;
}

// ---------------- reset ----------------
__global__ void reset_kernel() {
    int i = threadIdx.x;
    if (i < N_EXP) { g_cnt[i] = 0; g_fill[i] = 0; g_psum[i] = 0.f; }
}

// ---------------- rmsnorm ----------------
__global__ void rmsnorm_kernel(const float* __restrict__ xin,
                               const float* __restrict__ gamma,
                               int use_x1) {
    int t = blockIdx.x;
    const float* src = use_x1 ? (const float*)g_x1 : xin;
    const float4* xr = (const float4*)(src + (size_t)t * H_DIM);
    int tid = threadIdx.x;
    float4 v = xr[tid];
    float ss = v.x * v.x + v.y * v.y + v.z * v.z + v.w * v.w;
    int lane = tid & 31, wid = tid >> 5;
    #pragma unroll
    for (int o = 16; o > 0; o >>= 1) ss += __shfl_down_sync(0xffffffffu, ss, o);
    __shared__ float red[8];
    if (lane == 0) red[wid] = ss;
    __syncthreads();
    if (tid == 0) {
        float tot = 0.f;
        #pragma unroll
        for (int i = 0; i < 8; i++) tot += red[i];
        red[0] = rsqrtf(tot / (float)H_DIM + 1e-5f);
    }
    __syncthreads();
    float r = red[0];
    float4 g = ((const float4*)gamma)[tid];
    float4 out;
    out.x = v.x * r * g.x; out.y = v.y * r * g.y;
    out.z = v.z * r * g.z; out.w = v.w * r * g.w;
    ((float4*)(g_xn + (size_t)t * H_DIM))[tid] = out;
}

// ---------------- tf32 GEMM core (unchanged) ----------------
struct GemmSmem {
    const float* Arow[BM];
    uint32_t As[2][BM][ASTR];
    uint32_t Bs[2][BK][BSTR];
};

__device__ __forceinline__ void stage_load(
    GemmSmem& sm, int st, int k0,
    const float* ap, int ar, int ac,
    const float* __restrict__ B, int ldb, int bk, int bn)
{
    uint32_t da0 = (uint32_t)__cvta_generic_to_shared(&sm.As[st][ar][ac]);
    uint32_t da1 = (uint32_t)__cvta_generic_to_shared(&sm.As[st][ar][ac + 4]);
    uint32_t db0 = (uint32_t)__cvta_generic_to_shared(&sm.Bs[st][bk][bn]);
    uint32_t db1 = (uint32_t)__cvta_generic_to_shared(&sm.Bs[st][bk][bn + 4]);
    const float* bsrc = B + (size_t)(k0 + bk) * ldb + bn;
    cp16(da0, ap + k0 + ac);
    cp16(da1, ap + k0 + ac + 4);
    cp16(db0, bsrc);
    cp16(db1, bsrc + 4);
}

__device__ __forceinline__ void stage_compute(
    GemmSmem& sm, int st, float (&acc)[2][8][4],
    int wm, int wn, int lq, int kq)
{
    #pragma unroll
    for (int ks = 0; ks < 2; ks++) {
        uint32_t a[2][4], b[8][2];
        #pragma unroll
        for (int mt = 0; mt < 2; mt++) {
            int r = wm * 32 + mt * 16 + lq;
            a[mt][0] = sm.As[st][r    ][ks * 8 + kq];
            a[mt][1] = sm.As[st][r + 8][ks * 8 + kq];
            a[mt][2] = sm.As[st][r    ][ks * 8 + kq + 4];
            a[mt][3] = sm.As[st][r + 8][ks * 8 + kq + 4];
        }
        #pragma unroll
        for (int nt = 0; nt < 8; nt++) {
            int c = wn * 64 + nt * 8 + lq;
            b[nt][0] = sm.Bs[st][ks * 8 + kq    ][c];
            b[nt][1] = sm.Bs[st][ks * 8 + kq + 4][c];
        }
        #pragma unroll
        for (int mt = 0; mt < 2; mt++)
            #pragma unroll
            for (int nt = 0; nt < 8; nt++)
                mma_tf32(acc[mt][nt], a[mt], b[nt]);
    }
}

__device__ __forceinline__ void gemm_run(
    GemmSmem& sm, const float* __restrict__ B, int ldb, int K,
    float (&acc)[2][8][4], int tid)
{
    const int ar = tid >> 1, ac = (tid & 1) * 8;
    const int bk = tid >> 4, bn = (tid & 15) * 8;
    const int lane = tid & 31, warp = tid >> 5;
    const int wm = warp >> 1, wn = warp & 1;
    const int lq = lane >> 2, kq = lane & 3;

    const float* ap = sm.Arow[ar];
    if (!ap) ap = g_zero;

    stage_load(sm, 0, 0, ap, ar, ac, B, ldb, bk, bn);
    cp_commit();
    int st = 0;
    for (int k0 = 0; k0 < K; k0 += BK) {
        cp_wait0();
        __syncthreads();
        if (k0 + BK < K) {
            stage_load(sm, st ^ 1, k0 + BK, ap, ar, ac, B, ldb, bk, bn);
            cp_commit();
        }
        stage_compute(sm, st, acc, wm, wn, lq, kq);
        st ^= 1;
    }
}

// ---------------- QKV projection (swizzled G=16) ----------------
__global__ void gemm_qkv_kernel(const float* __restrict__ wq,
                                const float* __restrict__ wk,
                                const float* __restrict__ wv) {
    __shared__ GemmSmem sm;
    int tid = threadIdx.x;
    int rowb, colb;
    swizzle_rc(16, rowb, colb);
    int nb = colb * BN, mb = rowb * BM;
    const float* B = (blockIdx.z == 0 ? wq : (blockIdx.z == 1 ? wk : wv)) + nb;
    float* C = (blockIdx.z == 0 ? g_q : (blockIdx.z == 1 ? g_k : g_v));
    if (tid < BM) sm.Arow[tid] = g_xn + (size_t)(mb + tid) * H_DIM;
    __syncthreads();
    float acc[2][8][4] = {};
    gemm_run(sm, B, H_DIM, H_DIM, acc, tid);
    int lane = tid & 31, warp = tid >> 5;
    int wm = warp >> 1, wn = warp & 1;
    int lq = lane >> 2, kq = lane & 3;
    #pragma unroll
    for (int mt = 0; mt < 2; mt++) {
        int r0 = mb + wm * 32 + mt * 16 + lq;
        #pragma unroll
        for (int nt = 0; nt < 8; nt++) {
            int c0 = nb + wn * 64 + nt * 8 + 2 * kq;
            C[(size_t)r0 * H_DIM + c0]           = acc[mt][nt][0];
            C[(size_t)r0 * H_DIM + c0 + 1]       = acc[mt][nt][1];
            C[(size_t)(r0 + 8) * H_DIM + c0]     = acc[mt][nt][2];
            C[(size_t)(r0 + 8) * H_DIM + c0 + 1] = acc[mt][nt][3];
        }
    }
}

// ---------------- RoPE ----------------
__global__ void rope_kernel() {
    int gid = blockIdx.x * blockDim.x + threadIdx.x;
    if (gid >= T_TOK * N_HEAD * 32) return;
    int i = gid & 31;
    int n = (gid >> 5) & 15;
    int t = gid >> 9;
    int s = t & (SEQ - 1);
    float inv = __expf(-9.210340371976184f * ((float)i / 32.0f));
    float ang = (float)s * inv;
    float c = cosf(ang), si = sinf(ang);
    size_t base = (size_t)t * H_DIM + n * HEAD_D;
    {
        float x1 = g_q[base + i], x2 = g_q[base + 32 + i];
        g_q[base + i]      = x1 * c - x2 * si;
        g_q[base + 32 + i] = x2 * c + x1 * si;
    }
    {
        float x1 = g_k[base + i], x2 = g_k[base + 32 + i];
        g_k[base + i]      = x1 * c - x2 * si;
        g_k[base + 32 + i] = x2 * c + x1 * si;
    }
}

// ---------------- flash attention (unchanged, known-good) ----------------
__global__ void flash_kernel() {
    __shared__ float Ks[64][64];
    __shared__ float Vs[64][64];
    int qt = blockIdx.x, nh = blockIdx.y, b = blockIdx.z;
    int tid = threadIdx.x;
    int row = tid >> 1;
    int half = tid & 1;
    int warp = tid >> 5;
    int qrow = qt * 64 + row;
    int t = b * SEQ + qrow;
    float q[32], o[32];
    const float4* qp = (const float4*)(g_q + (size_t)t * H_DIM + nh * HEAD_D + half * 32);
    #pragma unroll
    for (int i = 0; i < 8; i++) {
        float4 v = qp[i];
        q[4 * i] = v.x; q[4 * i + 1] = v.y; q[4 * i + 2] = v.z; q[4 * i + 3] = v.w;
    }
    #pragma unroll
    for (int d = 0; d < 32; d++) o[d] = 0.f;
    float m = -1e30f, l = 0.f;
    for (int kt = 0; kt <= qt; kt++) {
        for (int idx = tid; idx < 64 * 64; idx += 128) {
            int r = idx >> 6, c = idx & 63;
            size_t src = (size_t)(b * SEQ + kt * 64 + r) * H_DIM + nh * HEAD_D + c;
            Ks[r][c] = g_k[src];
            Vs[r][c] = g_v[src];
        }
        __syncthreads();
        int jlim = (kt == qt) ? (warp * 16 + 16) : 64;
        for (int j = 0; j < jlim; j++) {
            int kglob = kt * 64 + j;
            const float* kr = &Ks[j][half * 32];
            float s0 = 0.f, s1 = 0.f, s2 = 0.f, s3 = 0.f;
            #pragma unroll
            for (int d = 0; d < 32; d += 4) {
                s0 += q[d]     * kr[d];
                s1 += q[d + 1] * kr[d + 1];
                s2 += q[d + 2] * kr[d + 2];
                s3 += q[d + 3] * kr[d + 3];
            }
            float part = s0 + s1 + s2 + s3;
            float s = (part + __shfl_xor_sync(0xffffffffu, part, 1)) * 0.125f;
            if (kglob > qrow) s = -1e30f;
            if (s > m) {
                float c = __expf(m - s);
                l *= c;
                #pragma unroll
                for (int d = 0; d < 32; d++) o[d] *= c;
                m = s;
            }
            float p = __expf(s - m);
            l += p;
            const float* vr = &Vs[j][half * 32];
            #pragma unroll
            for (int d = 0; d < 32; d++) o[d] += p * vr[d];
        }
        __syncthreads();
    }
    float invl = 1.0f / l;
    float* op = g_ao + (size_t)t * H_DIM + nh * HEAD_D + half * 32;
    #pragma unroll
    for (int d = 0; d < 32; d++) op[d] = o[d] * invl;
}

// ---------------- WO projection + residual (swizzled G=16) ----------------
__global__ void gemm_wo_kernel(const float* __restrict__ x,
                               const float* __restrict__ wo,
                               float* __restrict__ dout) {
    __shared__ GemmSmem sm;
    int tid = threadIdx.x;
    int rowb, colb;
    swizzle_rc(16, rowb, colb);
    int nb = colb * BN, mb = rowb * BM;
    if (tid < BM) sm.Arow[tid] = g_ao + (size_t)(mb + tid) * H_DIM;
    __syncthreads();
    float acc[2][8][4] = {};
    gemm_run(sm, wo + nb, H_DIM, H_DIM, acc, tid);
    int lane = tid & 31, warp = tid >> 5;
    int wm = warp >> 1, wn = warp & 1;
    int lq = lane >> 2, kq = lane & 3;
    #pragma unroll
    for (int mt = 0; mt < 2; mt++) {
        int r0 = mb + wm * 32 + mt * 16 + lq;
        #pragma unroll
        for (int nt = 0; nt < 8; nt++) {
            int c0 = nb + wn * 64 + nt * 8 + 2 * kq;
            #pragma unroll
            for (int h = 0; h < 2; h++) {
                size_t i0 = (size_t)(r0 + h * 8) * H_DIM + c0;
                float v0 = x[i0] + acc[mt][nt][h * 2];
                float v1 = x[i0 + 1] + acc[mt][nt][h * 2 + 1];
                g_x1[i0] = v0; g_x1[i0 + 1] = v1;
                dout[i0] = v0; dout[i0 + 1] = v1;
            }
        }
    }
}

// ---------------- router ----------------
__global__ void router_kernel(const float* __restrict__ wr) {
    int warp = (blockIdx.x * blockDim.x + threadIdx.x) >> 5;
    int lane = threadIdx.x & 31;
    if (warp >= T_TOK) return;
    const float* xr = g_xn + (size_t)warp * H_DIM;
    float acc[N_EXP];
    #pragma unroll
    for (int e = 0; e < N_EXP; e++) acc[e] = 0.f;
    for (int h = lane; h < H_DIM; h += 32) {
        float xv = xr[h];
        #pragma unroll
        for (int e = 0; e < N_EXP; e++) acc[e] += xv * wr[h * N_EXP + e];
    }
    #pragma unroll
    for (int e = 0; e < N_EXP; e++)
        #pragma unroll
        for (int o = 16; o > 0; o >>= 1)
            acc[e] += __shfl_down_sync(0xffffffffu, acc[e], o);
    if (lane == 0) {
        float mx = acc[0];
        #pragma unroll
        for (int e = 1; e < N_EXP; e++) mx = fmaxf(mx, acc[e]);
        float p[N_EXP], s = 0.f;
        #pragma unroll
        for (int e = 0; e < N_EXP; e++) { p[e] = expf(acc[e] - mx); s += p[e]; }
        float invs = 1.0f / s;
        #pragma unroll
        for (int e = 0; e < N_EXP; e++) p[e] *= invs;
        int i0 = 0;
        #pragma unroll
        for (int e = 1; e < N_EXP; e++) if (p[e] > p[i0]) i0 = e;
        int i1 = (i0 == 0) ? 1 : 0;
        #pragma unroll
        for (int e = 0; e < N_EXP; e++) if (e != i0 && p[e] > p[i1]) i1 = e;
        float w0 = p[i0], w1 = p[i1];
        float ws = 1.0f / (w0 + w1);
        g_topi[warp * 2] = i0;      g_topi[warp * 2 + 1] = i1;
        g_topw[warp * 2] = w0 * ws; g_topw[warp * 2 + 1] = w1 * ws;
        atomicAdd(&g_cnt[i0], 1);
        atomicAdd(&g_cnt[i1], 1);
        #pragma unroll
        for (int e = 0; e < N_EXP; e++) atomicAdd(&g_psum[e], p[e]);
    }
}

// ---------------- prefix + aux ----------------
__global__ void scan_kernel(float* __restrict__ dout, int write_aux) {
    if (threadIdx.x == 0) {
        int off = 0;
        float aux = 0.f;
        for (int e = 0; e < N_EXP; e++) { g_off[e] = off; off += g_cnt[e]; }
        for (int e = 0; e < N_EXP; e++) {
            float f = (float)g_cnt[e] / (float)(T_TOK * 2);
            float P = g_psum[e] / (float)T_TOK;
            aux += f * P;
        }
        aux *= (float)N_EXP;
        if (write_aux) dout[(size_t)T_TOK * H_DIM] = aux;
    }
}

// ---------------- gather lists ----------------
__global__ void fill_kernel() {
    int gid = blockIdx.x * blockDim.x + threadIdx.x;
    if (gid >= T_TOK * 2) return;
    int t = gid >> 1;
    int e = g_topi[gid];
    int pos = g_off[e] + atomicAdd(&g_fill[e], 1);
    g_slot_tok[pos] = t;
    g_slot_w[pos] = g_topw[gid];
}

// ---------------- MoE GEMM1 (swizzled G=4) ----------------
__global__ void moe_gemm1_kernel(const float* __restrict__ w1) {
    int e = blockIdx.z;
    int cnt = g_cnt[e];
    int rowb, colb;
    swizzle_rc(4, rowb, colb);
    int mt_ = rowb;
    if (mt_ * BM >= cnt) return;
    int off = g_off[e];
    __shared__ GemmSmem sm;
    int tid = threadIdx.x;
    if (tid < BM) {
        int rl = mt_ * BM + tid;
        sm.Arow[tid] = (rl < cnt) ? g_xn + (size_t)g_slot_tok[off + rl] * H_DIM : (const float*)0;
    }
    __syncthreads();
    int nb = colb * BN;
    const float* B = w1 + (size_t)e * H_DIM * F_DIM + nb;
    float acc[2][8][4] = {};
    gemm_run(sm, B, F_DIM, H_DIM, acc, tid);
    int lane = tid & 31, warp = tid >> 5;
    int wm = warp >> 1, wn = warp & 1;
    int lq = lane >> 2, kq = lane & 3;
    #pragma unroll
    for (int mt = 0; mt < 2; mt++) {
        #pragma unroll
        for (int h = 0; h < 2; h++) {
            int rl = mt_ * BM + wm * 32 + mt * 16 + lq + h * 8;
            if (rl >= cnt) continue;
            float* dst = g_h1 + (size_t)(off + rl) * F_DIM + nb;
            #pragma unroll
            for (int nt = 0; nt < 8; nt++) {
                int c0 = wn * 64 + nt * 8 + 2 * kq;
                dst[c0]     = gelu_tanh(acc[mt][nt][h * 2]);
                dst[c0 + 1] = gelu_tanh(acc[mt][nt][h * 2 + 1]);
            }
        }
    }
}

// ---------------- MoE GEMM2 (swizzled G=16) ----------------
__global__ void moe_gemm2_kernel(const float* __restrict__ w2,
                                 float* __restrict__ dout) {
    int e = blockIdx.z;
    int cnt = g_cnt[e];
    int rowb, colb;
    swizzle_rc(16, rowb, colb);
    int mt_ = rowb;
    if (mt_ * BM >= cnt) return;
    int off = g_off[e];
    __shared__ GemmSmem sm;
    int tid = threadIdx.x;
    if (tid < BM) {
        int rl = mt_ * BM + tid;
        sm.Arow[tid] = (rl < cnt) ? g_h1 + (size_t)(off + rl) * F_DIM : (const float*)0;
    }
    __syncthreads();
    int nb = colb * BN;
    const float* B = w2 + (size_t)e * F_DIM * H_DIM + nb;
    float acc[2][8][4] = {};
    gemm_run(sm, B, H_DIM, F_DIM, acc, tid);
    int lane = tid & 31, warp = tid >> 5;
    int wm = warp >> 1, wn = warp & 1;
    int lq = lane >> 2, kq = lane & 3;
    #pragma unroll
    for (int mt = 0; mt < 2; mt++) {
        #pragma unroll
        for (int h = 0; h < 2; h++) {
            int rl = mt_ * BM + wm * 32 + mt * 16 + lq + h * 8;
            if (rl >= cnt) continue;
            int tok = g_slot_tok[off + rl];
            float w = g_slot_w[off + rl];
            float* dst = dout + (size_t)tok * H_DIM + nb;
            #pragma unroll
            for (int nt = 0; nt < 8; nt++) {
                int c0 = wn * 64 + nt * 8 + 2 * kq;
                atomicAdd(&dst[c0],     w * acc[mt][nt][h * 2]);
                atomicAdd(&dst[c0 + 1], w * acc[mt][nt][h * 2 + 1]);
            }
        }
    }
}

// ---------------- launch ----------------
extern "C" void kernel_launch(void* const* d_in, const int* in_sizes, int n_in,
                              void* d_out, int out_size) {
    const float* x     = (const float*)d_in[0];
    const float* gattn = (const float*)d_in[1];
    const float* wq    = (const float*)d_in[2];
    const float* wk    = (const float*)d_in[3];
    const float* wv    = (const float*)d_in[4];
    const float* wo    = (const float*)d_in[5];
    const float* gffn  = (const float*)d_in[6];
    const float* wr    = (const float*)d_in[7];
    const float* w1    = (const float*)d_in[8];
    const float* w2    = (const float*)d_in[9];
    float* out = (float*)d_out;
    int write_aux = (out_size > T_TOK * H_DIM) ? 1 : 0;

    reset_kernel<<<1, 32>>>();

    rmsnorm_kernel<<<T_TOK, 256>>>(x, gattn, 0);
    {
        dim3 g(H_DIM / BN, T_TOK / BM, 3);
        gemm_qkv_kernel<<<g, 256>>>(wq, wk, wv);
    }
    {
        int nthr = T_TOK * N_HEAD * 32;
        rope_kernel<<<(nthr + 255) / 256, 256>>>();
    }
    {
        dim3 g(SEQ / 64, N_HEAD, BATCH);
        flash_kernel<<<g, 128>>>();
    }
    {
        dim3 g(H_DIM / BN, T_TOK / BM);
        gemm_wo_kernel<<<g, 256>>>(x, wo, out);
    }

    rmsnorm_kernel<<<T_TOK, 256>>>(x, gffn, 1);
    router_kernel<<<T_TOK / 4, 128>>>(wr);
    scan_kernel<<<1, 32>>>(out, write_aux);
    fill_kernel<<<(T_TOK * 2 + 255) / 256, 256>>>();
    {
        dim3 g(F_DIM / BN, T_TOK / BM, N_EXP);
        moe_gemm1_kernel<<<g, 256>>>(w1);
    }
    {
        dim3 g(H_DIM / BN, T_TOK / BM, N_EXP);
        moe_gemm2_kernel<<<g, 256>>>(w2, out);
    }
}

// round 16
// speedup vs baseline: 1.9592x; 1.9592x over previous
#include <cuda_runtime.h>
#include <math.h>
#include <stdint.h>

#define T_TOK   4096
#define H_DIM   1024
#define N_HEAD  16
#define HEAD_D  64
#define SEQ     1024
#define BATCH   4
#define F_DIM   4096
#define N_EXP   8
#define N_SLOTS (T_TOK * 2)

#define BM 128
#define BN 128
#define BK 16
#define ASTR 20
#define BSTR 136
#define FS 72   // flash smem row stride (floats): 72%32=8 -> conflict-light

// ---------------- scratch ----------------
__device__ float g_xn[T_TOK * H_DIM];
__device__ float g_q[T_TOK * H_DIM];
__device__ float g_k[T_TOK * H_DIM];
__device__ float g_v[T_TOK * H_DIM];
__device__ float g_ao[T_TOK * H_DIM];
__device__ float g_x1[T_TOK * H_DIM];
__device__ float g_h1[(size_t)N_SLOTS * F_DIM];
__device__ float g_zero[F_DIM];
__device__ int   g_cnt[N_EXP];
__device__ int   g_fill[N_EXP];
__device__ int   g_off[N_EXP];
__device__ float g_psum[N_EXP];
__device__ int   g_topi[T_TOK * 2];
__device__ float g_topw[T_TOK * 2];
__device__ int   g_slot_tok[N_SLOTS];
__device__ float g_slot_w[N_SLOTS];

// ---------------- helpers ----------------
__device__ __forceinline__ float gelu_tanh(float x) {
    float x3 = x * x * x;
    return 0.5f * x * (1.0f + tanhf(0.7978845608028654f * (x + 0.044715f * x3)));
}

__device__ __forceinline__ void mma_tf32(float (&c)[4], const uint32_t (&a)[4],
                                         const uint32_t (&b)[2]) {
    asm volatile(
        "mma.sync.aligned.m16n8k8.row.col.f32.tf32.tf32.f32 "
        "{%0,%1,%2,%3}, {%4,%5,%6,%7}, {%8,%9}, {%0,%1,%2,%3};"
        : "+f"(c[0]), "+f"(c[1]), "+f"(c[2]), "+f"(c[3])
        : "r"(a[0]), "r"(a[1]), "r"(a[2]), "r"(a[3]), "r"(b[0]), "r"(b[1]));
}

__device__ __forceinline__ void cp16(uint32_t dst, const void* src) {
    asm volatile("cp.async.cg.shared.global [%0], [%1], 16;"
                 :: "r"(dst), "l"(src));
}
__device__ __forceinline__ void cp_commit() { asm volatile("cp.async.commit_group;"); }
__device__ __forceinline__ void cp_wait0()  { asm volatile("cp.async.wait_group 0;"); }

__device__ __forceinline__ float f2tff(float f) {
    uint32_t r;
    asm("cvt.rna.tf32.f32 %0, %1;" : "=r"(r) : "f"(f));
    return __uint_as_float(r);
}

// ---------------- reset ----------------
__global__ void reset_kernel() {
    int i = threadIdx.x;
    if (i < N_EXP) { g_cnt[i] = 0; g_fill[i] = 0; g_psum[i] = 0.f; }
}

// ---------------- rmsnorm ----------------
__global__ void rmsnorm_kernel(const float* __restrict__ xin,
                               const float* __restrict__ gamma,
                               int use_x1) {
    int t = blockIdx.x;
    const float* src = use_x1 ? (const float*)g_x1 : xin;
    const float4* xr = (const float4*)(src + (size_t)t * H_DIM);
    int tid = threadIdx.x;
    float4 v = xr[tid];
    float ss = v.x * v.x + v.y * v.y + v.z * v.z + v.w * v.w;
    int lane = tid & 31, wid = tid >> 5;
    #pragma unroll
    for (int o = 16; o > 0; o >>= 1) ss += __shfl_down_sync(0xffffffffu, ss, o);
    __shared__ float red[8];
    if (lane == 0) red[wid] = ss;
    __syncthreads();
    if (tid == 0) {
        float tot = 0.f;
        #pragma unroll
        for (int i = 0; i < 8; i++) tot += red[i];
        red[0] = rsqrtf(tot / (float)H_DIM + 1e-5f);
    }
    __syncthreads();
    float r = red[0];
    float4 g = ((const float4*)gamma)[tid];
    float4 out;
    out.x = v.x * r * g.x; out.y = v.y * r * g.y;
    out.z = v.z * r * g.z; out.w = v.w * r * g.w;
    ((float4*)(g_xn + (size_t)t * H_DIM))[tid] = out;
}

// ---------------- tf32 GEMM core (R11, unchanged) ----------------
struct GemmSmem {
    const float* Arow[BM];
    uint32_t As[2][BM][ASTR];
    uint32_t Bs[2][BK][BSTR];
};

__device__ __forceinline__ void stage_load(
    GemmSmem& sm, int st, int k0,
    const float* ap, int ar, int ac,
    const float* __restrict__ B, int ldb, int bk, int bn)
{
    uint32_t da0 = (uint32_t)__cvta_generic_to_shared(&sm.As[st][ar][ac]);
    uint32_t da1 = (uint32_t)__cvta_generic_to_shared(&sm.As[st][ar][ac + 4]);
    uint32_t db0 = (uint32_t)__cvta_generic_to_shared(&sm.Bs[st][bk][bn]);
    uint32_t db1 = (uint32_t)__cvta_generic_to_shared(&sm.Bs[st][bk][bn + 4]);
    const float* bsrc = B + (size_t)(k0 + bk) * ldb + bn;
    cp16(da0, ap + k0 + ac);
    cp16(da1, ap + k0 + ac + 4);
    cp16(db0, bsrc);
    cp16(db1, bsrc + 4);
}

__device__ __forceinline__ void stage_compute(
    GemmSmem& sm, int st, float (&acc)[2][8][4],
    int wm, int wn, int lq, int kq)
{
    #pragma unroll
    for (int ks = 0; ks < 2; ks++) {
        uint32_t a[2][4], b[8][2];
        #pragma unroll
        for (int mt = 0; mt < 2; mt++) {
            int r = wm * 32 + mt * 16 + lq;
            a[mt][0] = sm.As[st][r    ][ks * 8 + kq];
            a[mt][1] = sm.As[st][r + 8][ks * 8 + kq];
            a[mt][2] = sm.As[st][r    ][ks * 8 + kq + 4];
            a[mt][3] = sm.As[st][r + 8][ks * 8 + kq + 4];
        }
        #pragma unroll
        for (int nt = 0; nt < 8; nt++) {
            int c = wn * 64 + nt * 8 + lq;
            b[nt][0] = sm.Bs[st][ks * 8 + kq    ][c];
            b[nt][1] = sm.Bs[st][ks * 8 + kq + 4][c];
        }
        #pragma unroll
        for (int mt = 0; mt < 2; mt++)
            #pragma unroll
            for (int nt = 0; nt < 8; nt++)
                mma_tf32(acc[mt][nt], a[mt], b[nt]);
    }
}

__device__ __forceinline__ void gemm_run(
    GemmSmem& sm, const float* __restrict__ B, int ldb, int K,
    float (&acc)[2][8][4], int tid)
{
    const int ar = tid >> 1, ac = (tid & 1) * 8;
    const int bk = tid >> 4, bn = (tid & 15) * 8;
    const int lane = tid & 31, warp = tid >> 5;
    const int wm = warp >> 1, wn = warp & 1;
    const int lq = lane >> 2, kq = lane & 3;

    const float* ap = sm.Arow[ar];
    if (!ap) ap = g_zero;

    stage_load(sm, 0, 0, ap, ar, ac, B, ldb, bk, bn);
    cp_commit();
    int st = 0;
    for (int k0 = 0; k0 < K; k0 += BK) {
        cp_wait0();
        __syncthreads();
        if (k0 + BK < K) {
            stage_load(sm, st ^ 1, k0 + BK, ap, ar, ac, B, ldb, bk, bn);
            cp_commit();
        }
        stage_compute(sm, st, acc, wm, wn, lq, kq);
        st ^= 1;
    }
}

// ---------------- QKV projection (original grid order) ----------------
__global__ void gemm_qkv_kernel(const float* __restrict__ wq,
                                const float* __restrict__ wk,
                                const float* __restrict__ wv) {
    __shared__ GemmSmem sm;
    int tid = threadIdx.x;
    int nb = blockIdx.x * BN, mb = blockIdx.y * BM;
    const float* B = (blockIdx.z == 0 ? wq : (blockIdx.z == 1 ? wk : wv)) + nb;
    float* C = (blockIdx.z == 0 ? g_q : (blockIdx.z == 1 ? g_k : g_v));
    if (tid < BM) sm.Arow[tid] = g_xn + (size_t)(mb + tid) * H_DIM;
    __syncthreads();
    float acc[2][8][4] = {};
    gemm_run(sm, B, H_DIM, H_DIM, acc, tid);
    int lane = tid & 31, warp = tid >> 5;
    int wm = warp >> 1, wn = warp & 1;
    int lq = lane >> 2, kq = lane & 3;
    #pragma unroll
    for (int mt = 0; mt < 2; mt++) {
        int r0 = mb + wm * 32 + mt * 16 + lq;
        #pragma unroll
        for (int nt = 0; nt < 8; nt++) {
            int c0 = nb + wn * 64 + nt * 8 + 2 * kq;
            C[(size_t)r0 * H_DIM + c0]           = acc[mt][nt][0];
            C[(size_t)r0 * H_DIM + c0 + 1]       = acc[mt][nt][1];
            C[(size_t)(r0 + 8) * H_DIM + c0]     = acc[mt][nt][2];
            C[(size_t)(r0 + 8) * H_DIM + c0 + 1] = acc[mt][nt][3];
        }
    }
}

// ---------------- RoPE ----------------
__global__ void rope_kernel() {
    int gid = blockIdx.x * blockDim.x + threadIdx.x;
    if (gid >= T_TOK * N_HEAD * 32) return;
    int i = gid & 31;
    int n = (gid >> 5) & 15;
    int t = gid >> 9;
    int s = t & (SEQ - 1);
    float inv = __expf(-9.210340371976184f * ((float)i / 32.0f));
    float ang = (float)s * inv;
    float c = cosf(ang), si = sinf(ang);
    size_t base = (size_t)t * H_DIM + n * HEAD_D;
    {
        float x1 = g_q[base + i], x2 = g_q[base + 32 + i];
        g_q[base + i]      = x1 * c - x2 * si;
        g_q[base + 32 + i] = x2 * c + x1 * si;
    }
    {
        float x1 = g_k[base + i], x2 = g_k[base + 32 + i];
        g_k[base + i]      = x1 * c - x2 * si;
        g_k[base + 32 + i] = x2 * c + x1 * si;
    }
}

// =====================================================================
// flash attention, tf32 tensor cores. Block=(qt,nh,b), 128 thr / 4 warps.
// Warp w owns q-rows 16w..16w+15. KP holds K^T ([dim][key]) during QK,
// then P ([row][key]) for PV (overlay, warp-private rows). Vs natural.
// Same m16n8k8 fragment layout as gemm core. All loops warp-uniform.
// =====================================================================
__global__ void flash_kernel() {
    __shared__ __align__(16) float KP[64][FS];
    __shared__ __align__(16) float Vs[64][FS];
    int qt = blockIdx.x, nh = blockIdx.y, b = blockIdx.z;
    int tid = threadIdx.x, lane = tid & 31, w = tid >> 5;
    int lq = lane >> 2, kq = lane & 3;
    int lrow = tid >> 1, lhalf = tid & 1;

    // stage Q (scaled 1/8, rna) into KP, then build A-fragments
    {
        const float* src = g_q + (size_t)(b * SEQ + qt * 64 + lrow) * H_DIM
                         + nh * HEAD_D + lhalf * 32;
        #pragma unroll
        for (int i = 0; i < 8; i++) {
            float4 v = *(const float4*)(src + i * 4);
            int d = lhalf * 32 + i * 4;
            KP[lrow][d]     = f2tff(v.x * 0.125f);
            KP[lrow][d + 1] = f2tff(v.y * 0.125f);
            KP[lrow][d + 2] = f2tff(v.z * 0.125f);
            KP[lrow][d + 3] = f2tff(v.w * 0.125f);
        }
    }
    __syncthreads();
    uint32_t qf[8][4];
    #pragma unroll
    for (int kc = 0; kc < 8; kc++) {
        qf[kc][0] = __float_as_uint(KP[w * 16 + lq    ][kc * 8 + kq]);
        qf[kc][1] = __float_as_uint(KP[w * 16 + lq + 8][kc * 8 + kq]);
        qf[kc][2] = __float_as_uint(KP[w * 16 + lq    ][kc * 8 + kq + 4]);
        qf[kc][3] = __float_as_uint(KP[w * 16 + lq + 8][kc * 8 + kq + 4]);
    }

    float o[8][4];
    #pragma unroll
    for (int nt = 0; nt < 8; nt++)
        o[nt][0] = o[nt][1] = o[nt][2] = o[nt][3] = 0.f;
    float m0 = -1e30f, m1 = -1e30f, l0 = 0.f, l1 = 0.f;

    for (int kt = 0; kt <= qt; kt++) {
        __syncthreads();   // prior-tile reads done (incl. Q-frag reads)
        {
            const float* ks = g_k + (size_t)(b * SEQ + kt * 64 + lrow) * H_DIM
                            + nh * HEAD_D + lhalf * 32;
            const float* vs = g_v + (size_t)(b * SEQ + kt * 64 + lrow) * H_DIM
                            + nh * HEAD_D + lhalf * 32;
            #pragma unroll
            for (int i = 0; i < 8; i++) {
                float4 kv = *(const float4*)(ks + i * 4);
                int d = lhalf * 32 + i * 4;
                KP[d    ][lrow] = f2tff(kv.x);
                KP[d + 1][lrow] = f2tff(kv.y);
                KP[d + 2][lrow] = f2tff(kv.z);
                KP[d + 3][lrow] = f2tff(kv.w);
                float4 vv = *(const float4*)(vs + i * 4);
                Vs[lrow][d]     = f2tff(vv.x);
                Vs[lrow][d + 1] = f2tff(vv.y);
                Vs[lrow][d + 2] = f2tff(vv.z);
                Vs[lrow][d + 3] = f2tff(vv.w);
            }
        }
        __syncthreads();

        // S = Q K^T
        float s[8][4];
        #pragma unroll
        for (int nt = 0; nt < 8; nt++)
            s[nt][0] = s[nt][1] = s[nt][2] = s[nt][3] = 0.f;
        #pragma unroll
        for (int kc = 0; kc < 8; kc++) {
            uint32_t bf[8][2];
            #pragma unroll
            for (int nt = 0; nt < 8; nt++) {
                bf[nt][0] = __float_as_uint(KP[kc * 8 + kq    ][nt * 8 + lq]);
                bf[nt][1] = __float_as_uint(KP[kc * 8 + kq + 4][nt * 8 + lq]);
            }
            #pragma unroll
            for (int nt = 0; nt < 8; nt++)
                mma_tf32(s[nt], qf[kc], bf[nt]);
        }

        // causal mask, arithmetic
        if (kt == qt) {
            int q0 = w * 16 + lq, q1 = q0 + 8;
            #pragma unroll
            for (int nt = 0; nt < 8; nt++) {
                int c = nt * 8 + 2 * kq;
                if (c     > q0) s[nt][0] = -1e30f;
                if (c + 1 > q0) s[nt][1] = -1e30f;
                if (c     > q1) s[nt][2] = -1e30f;
                if (c + 1 > q1) s[nt][3] = -1e30f;
            }
        }

        // online softmax (row groups lq / lq+8; reduce over kq lanes)
        float mx0 = -1e30f, mx1 = -1e30f;
        #pragma unroll
        for (int nt = 0; nt < 8; nt++) {
            mx0 = fmaxf(mx0, fmaxf(s[nt][0], s[nt][1]));
            mx1 = fmaxf(mx1, fmaxf(s[nt][2], s[nt][3]));
        }
        mx0 = fmaxf(mx0, __shfl_xor_sync(0xffffffffu, mx0, 1));
        mx0 = fmaxf(mx0, __shfl_xor_sync(0xffffffffu, mx0, 2));
        mx1 = fmaxf(mx1, __shfl_xor_sync(0xffffffffu, mx1, 1));
        mx1 = fmaxf(mx1, __shfl_xor_sync(0xffffffffu, mx1, 2));
        float nm0 = fmaxf(m0, mx0), nm1 = fmaxf(m1, mx1);
        float f0 = __expf(m0 - nm0), f1 = __expf(m1 - nm1);
        m0 = nm0; m1 = nm1;
        float ps0 = 0.f, ps1 = 0.f;
        #pragma unroll
        for (int nt = 0; nt < 8; nt++) {
            s[nt][0] = f2tff(__expf(s[nt][0] - m0)); ps0 += s[nt][0];
            s[nt][1] = f2tff(__expf(s[nt][1] - m0)); ps0 += s[nt][1];
            s[nt][2] = f2tff(__expf(s[nt][2] - m1)); ps1 += s[nt][2];
            s[nt][3] = f2tff(__expf(s[nt][3] - m1)); ps1 += s[nt][3];
        }
        ps0 += __shfl_xor_sync(0xffffffffu, ps0, 1);
        ps0 += __shfl_xor_sync(0xffffffffu, ps0, 2);
        ps1 += __shfl_xor_sync(0xffffffffu, ps1, 1);
        ps1 += __shfl_xor_sync(0xffffffffu, ps1, 2);
        l0 = l0 * f0 + ps0;
        l1 = l1 * f1 + ps1;
        #pragma unroll
        for (int nt = 0; nt < 8; nt++) {
            o[nt][0] *= f0; o[nt][1] *= f0;
            o[nt][2] *= f1; o[nt][3] *= f1;
        }

        __syncthreads();   // all warps done reading KP before P overlay
        {
            float* p0 = &KP[w * 16 + lq    ][2 * kq];
            float* p1 = &KP[w * 16 + lq + 8][2 * kq];
            #pragma unroll
            for (int nt = 0; nt < 8; nt++) {
                p0[nt * 8]     = s[nt][0];
                p0[nt * 8 + 1] = s[nt][1];
                p1[nt * 8]     = s[nt][2];
                p1[nt * 8 + 1] = s[nt][3];
            }
        }
        __syncwarp();

        // O += P V   (A = warp-private KP rows, B = Vs natural)
        #pragma unroll
        for (int kc = 0; kc < 8; kc++) {
            uint32_t pa[4];
            pa[0] = __float_as_uint(KP[w * 16 + lq    ][kc * 8 + kq]);
            pa[1] = __float_as_uint(KP[w * 16 + lq + 8][kc * 8 + kq]);
            pa[2] = __float_as_uint(KP[w * 16 + lq    ][kc * 8 + kq + 4]);
            pa[3] = __float_as_uint(KP[w * 16 + lq + 8][kc * 8 + kq + 4]);
            uint32_t bv[8][2];
            #pragma unroll
            for (int nt = 0; nt < 8; nt++) {
                bv[nt][0] = __float_as_uint(Vs[kc * 8 + kq    ][nt * 8 + lq]);
                bv[nt][1] = __float_as_uint(Vs[kc * 8 + kq + 4][nt * 8 + lq]);
            }
            #pragma unroll
            for (int nt = 0; nt < 8; nt++)
                mma_tf32(o[nt], pa, bv[nt]);
        }
    }

    float i0 = 1.f / l0, i1 = 1.f / l1;
    float* o0 = g_ao + (size_t)(b * SEQ + qt * 64 + w * 16 + lq) * H_DIM
              + nh * HEAD_D + 2 * kq;
    float* o1 = o0 + (size_t)8 * H_DIM;
    #pragma unroll
    for (int nt = 0; nt < 8; nt++) {
        o0[nt * 8]     = o[nt][0] * i0;
        o0[nt * 8 + 1] = o[nt][1] * i0;
        o1[nt * 8]     = o[nt][2] * i1;
        o1[nt * 8 + 1] = o[nt][3] * i1;
    }
}

// ---------------- WO projection + residual ----------------
__global__ void gemm_wo_kernel(const float* __restrict__ x,
                               const float* __restrict__ wo,
                               float* __restrict__ dout) {
    __shared__ GemmSmem sm;
    int tid = threadIdx.x;
    int nb = blockIdx.x * BN, mb = blockIdx.y * BM;
    if (tid < BM) sm.Arow[tid] = g_ao + (size_t)(mb + tid) * H_DIM;
    __syncthreads();
    float acc[2][8][4] = {};
    gemm_run(sm, wo + nb, H_DIM, H_DIM, acc, tid);
    int lane = tid & 31, warp = tid >> 5;
    int wm = warp >> 1, wn = warp & 1;
    int lq = lane >> 2, kq = lane & 3;
    #pragma unroll
    for (int mt = 0; mt < 2; mt++) {
        int r0 = mb + wm * 32 + mt * 16 + lq;
        #pragma unroll
        for (int nt = 0; nt < 8; nt++) {
            int c0 = nb + wn * 64 + nt * 8 + 2 * kq;
            #pragma unroll
            for (int h = 0; h < 2; h++) {
                size_t i0 = (size_t)(r0 + h * 8) * H_DIM + c0;
                float v0 = x[i0] + acc[mt][nt][h * 2];
                float v1 = x[i0 + 1] + acc[mt][nt][h * 2 + 1];
                g_x1[i0] = v0; g_x1[i0 + 1] = v1;
                dout[i0] = v0; dout[i0 + 1] = v1;
            }
        }
    }
}

// ---------------- router ----------------
__global__ void router_kernel(const float* __restrict__ wr) {
    int warp = (blockIdx.x * blockDim.x + threadIdx.x) >> 5;
    int lane = threadIdx.x & 31;
    if (warp >= T_TOK) return;
    const float* xr = g_xn + (size_t)warp * H_DIM;
    float acc[N_EXP];
    #pragma unroll
    for (int e = 0; e < N_EXP; e++) acc[e] = 0.f;
    for (int h = lane; h < H_DIM; h += 32) {
        float xv = xr[h];
        #pragma unroll
        for (int e = 0; e < N_EXP; e++) acc[e] += xv * wr[h * N_EXP + e];
    }
    #pragma unroll
    for (int e = 0; e < N_EXP; e++)
        #pragma unroll
        for (int o = 16; o > 0; o >>= 1)
            acc[e] += __shfl_down_sync(0xffffffffu, acc[e], o);
    if (lane == 0) {
        float mx = acc[0];
        #pragma unroll
        for (int e = 1; e < N_EXP; e++) mx = fmaxf(mx, acc[e]);
        float p[N_EXP], s = 0.f;
        #pragma unroll
        for (int e = 0; e < N_EXP; e++) { p[e] = expf(acc[e] - mx); s += p[e]; }
        float invs = 1.0f / s;
        #pragma unroll
        for (int e = 0; e < N_EXP; e++) p[e] *= invs;
        int i0 = 0;
        #pragma unroll
        for (int e = 1; e < N_EXP; e++) if (p[e] > p[i0]) i0 = e;
        int i1 = (i0 == 0) ? 1 : 0;
        #pragma unroll
        for (int e = 0; e < N_EXP; e++) if (e != i0 && p[e] > p[i1]) i1 = e;
        float w0 = p[i0], w1 = p[i1];
        float ws = 1.0f / (w0 + w1);
        g_topi[warp * 2] = i0;      g_topi[warp * 2 + 1] = i1;
        g_topw[warp * 2] = w0 * ws; g_topw[warp * 2 + 1] = w1 * ws;
        atomicAdd(&g_cnt[i0], 1);
        atomicAdd(&g_cnt[i1], 1);
        #pragma unroll
        for (int e = 0; e < N_EXP; e++) atomicAdd(&g_psum[e], p[e]);
    }
}

// ---------------- prefix + aux ----------------
__global__ void scan_kernel(float* __restrict__ dout, int write_aux) {
    if (threadIdx.x == 0) {
        int off = 0;
        float aux = 0.f;
        for (int e = 0; e < N_EXP; e++) { g_off[e] = off; off += g_cnt[e]; }
        for (int e = 0; e < N_EXP; e++) {
            float f = (float)g_cnt[e] / (float)(T_TOK * 2);
            float P = g_psum[e] / (float)T_TOK;
            aux += f * P;
        }
        aux *= (float)N_EXP;
        if (write_aux) dout[(size_t)T_TOK * H_DIM] = aux;
    }
}

// ---------------- gather lists ----------------
__global__ void fill_kernel() {
    int gid = blockIdx.x * blockDim.x + threadIdx.x;
    if (gid >= T_TOK * 2) return;
    int t = gid >> 1;
    int e = g_topi[gid];
    int pos = g_off[e] + atomicAdd(&g_fill[e], 1);
    g_slot_tok[pos] = t;
    g_slot_w[pos] = g_topw[gid];
}

// ---------------- MoE GEMM1 (original grid order) ----------------
__global__ void moe_gemm1_kernel(const float* __restrict__ w1) {
    int e = blockIdx.z;
    int cnt = g_cnt[e];
    int mt_ = blockIdx.y;
    if (mt_ * BM >= cnt) return;
    int off = g_off[e];
    __shared__ GemmSmem sm;
    int tid = threadIdx.x;
    if (tid < BM) {
        int rl = mt_ * BM + tid;
        sm.Arow[tid] = (rl < cnt) ? g_xn + (size_t)g_slot_tok[off + rl] * H_DIM : (const float*)0;
    }
    __syncthreads();
    int nb = blockIdx.x * BN;
    const float* B = w1 + (size_t)e * H_DIM * F_DIM + nb;
    float acc[2][8][4] = {};
    gemm_run(sm, B, F_DIM, H_DIM, acc, tid);
    int lane = tid & 31, warp = tid >> 5;
    int wm = warp >> 1, wn = warp & 1;
    int lq = lane >> 2, kq = lane & 3;
    #pragma unroll
    for (int mt = 0; mt < 2; mt++) {
        #pragma unroll
        for (int h = 0; h < 2; h++) {
            int rl = mt_ * BM + wm * 32 + mt * 16 + lq + h * 8;
            if (rl >= cnt) continue;
            float* dst = g_h1 + (size_t)(off + rl) * F_DIM + nb;
            #pragma unroll
            for (int nt = 0; nt < 8; nt++) {
                int c0 = wn * 64 + nt * 8 + 2 * kq;
                dst[c0]     = gelu_tanh(acc[mt][nt][h * 2]);
                dst[c0 + 1] = gelu_tanh(acc[mt][nt][h * 2 + 1]);
            }
        }
    }
}

// ---------------- MoE GEMM2 (original grid order) ----------------
__global__ void moe_gemm2_kernel(const float* __restrict__ w2,
                                 float* __restrict__ dout) {
    int e = blockIdx.z;
    int cnt = g_cnt[e];
    int mt_ = blockIdx.y;
    if (mt_ * BM >= cnt) return;
    int off = g_off[e];
    __shared__ GemmSmem sm;
    int tid = threadIdx.x;
    if (tid < BM) {
        int rl = mt_ * BM + tid;
        sm.Arow[tid] = (rl < cnt) ? g_h1 + (size_t)(off + rl) * F_DIM : (const float*)0;
    }
    __syncthreads();
    int nb = blockIdx.x * BN;
    const float* B = w2 + (size_t)e * F_DIM * H_DIM + nb;
    float acc[2][8][4] = {};
    gemm_run(sm, B, H_DIM, F_DIM, acc, tid);
    int lane = tid & 31, warp = tid >> 5;
    int wm = warp >> 1, wn = warp & 1;
    int lq = lane >> 2, kq = lane & 3;
    #pragma unroll
    for (int mt = 0; mt < 2; mt++) {
        #pragma unroll
        for (int h = 0; h < 2; h++) {
            int rl = mt_ * BM + wm * 32 + mt * 16 + lq + h * 8;
            if (rl >= cnt) continue;
            int tok = g_slot_tok[off + rl];
            float w = g_slot_w[off + rl];
            float* dst = dout + (size_t)tok * H_DIM + nb;
            #pragma unroll
            for (int nt = 0; nt < 8; nt++) {
                int c0 = wn * 64 + nt * 8 + 2 * kq;
                atomicAdd(&dst[c0],     w * acc[mt][nt][h * 2]);
                atomicAdd(&dst[c0 + 1], w * acc[mt][nt][h * 2 + 1]);
            }
        }
    }
}

// ---------------- launch ----------------
extern "C" void kernel_launch(void* const* d_in, const int* in_sizes, int n_in,
                              void* d_out, int out_size) {
    const float* x     = (const float*)d_in[0];
    const float* gattn = (const float*)d_in[1];
    const float* wq    = (const float*)d_in[2];
    const float* wk    = (const float*)d_in[3];
    const float* wv    = (const float*)d_in[4];
    const float* wo    = (const float*)d_in[5];
    const float* gffn  = (const float*)d_in[6];
    const float* wr    = (const float*)d_in[7];
    const float* w1    = (const float*)d_in[8];
    const float* w2    = (const float*)d_in[9];
    float* out = (float*)d_out;
    int write_aux = (out_size > T_TOK * H_DIM) ? 1 : 0;

    reset_kernel<<<1, 32>>>();

    rmsnorm_kernel<<<T_TOK, 256>>>(x, gattn, 0);
    {
        dim3 g(H_DIM / BN, T_TOK / BM, 3);
        gemm_qkv_kernel<<<g, 256>>>(wq, wk, wv);
    }
    {
        int nthr = T_TOK * N_HEAD * 32;
        rope_kernel<<<(nthr + 255) / 256, 256>>>();
    }
    {
        dim3 g(SEQ / 64, N_HEAD, BATCH);
        flash_kernel<<<g, 128>>>();
    }
    {
        dim3 g(H_DIM / BN, T_TOK / BM);
        gemm_wo_kernel<<<g, 256>>>(x, wo, out);
    }

    rmsnorm_kernel<<<T_TOK, 256>>>(x, gffn, 1);
    router_kernel<<<T_TOK / 4, 128>>>(wr);
    scan_kernel<<<1, 32>>>(out, write_aux);
    fill_kernel<<<(T_TOK * 2 + 255) / 256, 256>>>();
    {
        dim3 g(F_DIM / BN, T_TOK / BM, N_EXP);
        moe_gemm1_kernel<<<g, 256>>>(w1);
    }
    {
        dim3 g(H_DIM / BN, T_TOK / BM, N_EXP);
        moe_gemm2_kernel<<<g, 256>>>(w2, out);
    }
}

// round 17
// speedup vs baseline: 2.8314x; 1.4452x over previous
#include <cuda_runtime.h>
#include <cuda_fp16.h>
#include <math.h>
#include <stdint.h>

#define T_TOK   4096
#define H_DIM   1024
#define N_HEAD  16
#define HEAD_D  64
#define SEQ     1024
#define BATCH   4
#define F_DIM   4096
#define N_EXP   8
#define N_SLOTS (T_TOK * 2)

#define BM 128
#define BN 128
#define ASTR 20
#define BSTR 136
#define FS 72

// ---------------- scratch ----------------
__device__ float    g_xn[T_TOK * H_DIM];           // fp32 (router)
__device__ uint32_t g_xnh[T_TOK * (H_DIM / 2)];    // packed half2
__device__ float    g_q[T_TOK * H_DIM];
__device__ float    g_k[T_TOK * H_DIM];
__device__ float    g_v[T_TOK * H_DIM];
__device__ uint32_t g_aoh[T_TOK * (H_DIM / 2)];
__device__ float    g_x1[T_TOK * H_DIM];
__device__ uint32_t g_h1h[(size_t)N_SLOTS * (F_DIM / 2)];
__device__ uint32_t g_zeroh[F_DIM / 2];            // zero-init padded-row src
// packed half2 weights: [K/2][N] per matrix
__device__ uint32_t g_wqh[(H_DIM / 2) * H_DIM];
__device__ uint32_t g_wkh[(H_DIM / 2) * H_DIM];
__device__ uint32_t g_wvh[(H_DIM / 2) * H_DIM];
__device__ uint32_t g_woh[(H_DIM / 2) * H_DIM];
__device__ uint32_t g_w1h[(size_t)N_EXP * (H_DIM / 2) * F_DIM];
__device__ uint32_t g_w2h[(size_t)N_EXP * (F_DIM / 2) * H_DIM];
__device__ int   g_cnt[N_EXP];
__device__ int   g_fill[N_EXP];
__device__ int   g_off[N_EXP];
__device__ float g_psum[N_EXP];
__device__ int   g_topi[T_TOK * 2];
__device__ float g_topw[T_TOK * 2];
__device__ int   g_slot_tok[N_SLOTS];
__device__ float g_slot_w[N_SLOTS];

// ---------------- helpers ----------------
__device__ __forceinline__ float gelu_tanh(float x) {
    float x3 = x * x * x;
    return 0.5f * x * (1.0f + tanhf(0.7978845608028654f * (x + 0.044715f * x3)));
}

__device__ __forceinline__ void mma_f16(float (&c)[4], const uint32_t (&a)[4],
                                        const uint32_t (&b)[2]) {
    asm volatile(
        "mma.sync.aligned.m16n8k16.row.col.f32.f16.f16.f32 "
        "{%0,%1,%2,%3}, {%4,%5,%6,%7}, {%8,%9}, {%0,%1,%2,%3};"
        : "+f"(c[0]), "+f"(c[1]), "+f"(c[2]), "+f"(c[3])
        : "r"(a[0]), "r"(a[1]), "r"(a[2]), "r"(a[3]), "r"(b[0]), "r"(b[1]));
}

__device__ __forceinline__ void mma_tf32(float (&c)[4], const uint32_t (&a)[4],
                                         const uint32_t (&b)[2]) {
    asm volatile(
        "mma.sync.aligned.m16n8k8.row.col.f32.tf32.tf32.f32 "
        "{%0,%1,%2,%3}, {%4,%5,%6,%7}, {%8,%9}, {%0,%1,%2,%3};"
        : "+f"(c[0]), "+f"(c[1]), "+f"(c[2]), "+f"(c[3])
        : "r"(a[0]), "r"(a[1]), "r"(a[2]), "r"(a[3]), "r"(b[0]), "r"(b[1]));
}

__device__ __forceinline__ void cp16(uint32_t dst, const void* src) {
    asm volatile("cp.async.cg.shared.global [%0], [%1], 16;"
                 :: "r"(dst), "l"(src));
}
__device__ __forceinline__ void cp_commit() { asm volatile("cp.async.commit_group;"); }
__device__ __forceinline__ void cp_wait0()  { asm volatile("cp.async.wait_group 0;"); }

__device__ __forceinline__ float f2tff(float f) {
    uint32_t r;
    asm("cvt.rna.tf32.f32 %0, %1;" : "=r"(r) : "f"(f));
    return __uint_as_float(r);
}

__device__ __forceinline__ uint32_t pack_h2(float lo, float hi) {
    __half2 h = __floats2half2_rn(lo, hi);
    return *(uint32_t*)&h;
}

// ---------------- weight conversion: fp32 [K][N] -> half2-packed [K/2][N] ----------------
__global__ void cvt_pack_kernel(const float* __restrict__ src,
                                uint32_t* __restrict__ dst,
                                size_t total, int n) {
    size_t i = (size_t)blockIdx.x * blockDim.x + threadIdx.x;
    if (i >= total) return;
    size_t p = i / (size_t)n;
    int c = (int)(i - p * (size_t)n);
    float lo = src[(2 * p) * (size_t)n + c];
    float hi = src[(2 * p + 1) * (size_t)n + c];
    dst[i] = pack_h2(lo, hi);
}

// ---------------- reset ----------------
__global__ void reset_kernel() {
    int i = threadIdx.x;
    if (i < N_EXP) { g_cnt[i] = 0; g_fill[i] = 0; g_psum[i] = 0.f; }
}

// ---------------- rmsnorm: fp32 out + packed half out ----------------
__global__ void rmsnorm_kernel(const float* __restrict__ xin,
                               const float* __restrict__ gamma,
                               int use_x1) {
    int t = blockIdx.x;
    const float* src = use_x1 ? (const float*)g_x1 : xin;
    const float4* xr = (const float4*)(src + (size_t)t * H_DIM);
    int tid = threadIdx.x;
    float4 v = xr[tid];
    float ss = v.x * v.x + v.y * v.y + v.z * v.z + v.w * v.w;
    int lane = tid & 31, wid = tid >> 5;
    #pragma unroll
    for (int o = 16; o > 0; o >>= 1) ss += __shfl_down_sync(0xffffffffu, ss, o);
    __shared__ float red[8];
    if (lane == 0) red[wid] = ss;
    __syncthreads();
    if (tid == 0) {
        float tot = 0.f;
        #pragma unroll
        for (int i = 0; i < 8; i++) tot += red[i];
        red[0] = rsqrtf(tot / (float)H_DIM + 1e-5f);
    }
    __syncthreads();
    float r = red[0];
    float4 g = ((const float4*)gamma)[tid];
    float4 out;
    out.x = v.x * r * g.x; out.y = v.y * r * g.y;
    out.z = v.z * r * g.z; out.w = v.w * r * g.w;
    ((float4*)(g_xn + (size_t)t * H_DIM))[tid] = out;
    g_xnh[(size_t)t * (H_DIM / 2) + 2 * tid]     = pack_h2(out.x, out.y);
    g_xnh[(size_t)t * (H_DIM / 2) + 2 * tid + 1] = pack_h2(out.z, out.w);
}

// =====================================================================
// fp16 GEMM core: BM=128 x BN=128, chunk = 16 packed rows (32 k-halves),
// 256 threads, 8 warps (4x2), warp tile 32x64, m16n8k16.
// A/B are half2-packed uint32 arrays; indexing identical to tf32 core.
// =====================================================================
struct GemmSmem {
    const uint32_t* Arow[BM];
    uint32_t As[2][BM][ASTR];
    uint32_t Bs[2][16][BSTR];
};

__device__ __forceinline__ void stage_load(
    GemmSmem& sm, int st, int k0p,
    const uint32_t* ap, int ar, int ac,
    const uint32_t* __restrict__ B, int ldb, int bk, int bn)
{
    uint32_t da0 = (uint32_t)__cvta_generic_to_shared(&sm.As[st][ar][ac]);
    uint32_t da1 = (uint32_t)__cvta_generic_to_shared(&sm.As[st][ar][ac + 4]);
    uint32_t db0 = (uint32_t)__cvta_generic_to_shared(&sm.Bs[st][bk][bn]);
    uint32_t db1 = (uint32_t)__cvta_generic_to_shared(&sm.Bs[st][bk][bn + 4]);
    const uint32_t* bsrc = B + (size_t)(k0p + bk) * ldb + bn;
    cp16(da0, ap + k0p + ac);
    cp16(da1, ap + k0p + ac + 4);
    cp16(db0, bsrc);
    cp16(db1, bsrc + 4);
}

__device__ __forceinline__ void stage_compute(
    GemmSmem& sm, int st, float (&acc)[2][8][4],
    int wm, int wn, int lq, int kq)
{
    #pragma unroll
    for (int ks = 0; ks < 2; ks++) {
        uint32_t a[2][4], b[8][2];
        #pragma unroll
        for (int mt = 0; mt < 2; mt++) {
            int r = wm * 32 + mt * 16 + lq;
            a[mt][0] = sm.As[st][r    ][ks * 8 + kq];
            a[mt][1] = sm.As[st][r + 8][ks * 8 + kq];
            a[mt][2] = sm.As[st][r    ][ks * 8 + kq + 4];
            a[mt][3] = sm.As[st][r + 8][ks * 8 + kq + 4];
        }
        #pragma unroll
        for (int nt = 0; nt < 8; nt++) {
            int c = wn * 64 + nt * 8 + lq;
            b[nt][0] = sm.Bs[st][ks * 8 + kq    ][c];
            b[nt][1] = sm.Bs[st][ks * 8 + kq + 4][c];
        }
        #pragma unroll
        for (int mt = 0; mt < 2; mt++)
            #pragma unroll
            for (int nt = 0; nt < 8; nt++)
                mma_f16(acc[mt][nt], a[mt], b[nt]);
    }
}

// Kp = total packed k rows (K/2); chunk = 16 packed rows
__device__ __forceinline__ void gemm_run(
    GemmSmem& sm, const uint32_t* __restrict__ B, int ldb, int Kp,
    float (&acc)[2][8][4], int tid)
{
    const int ar = tid >> 1, ac = (tid & 1) * 8;
    const int bk = tid >> 4, bn = (tid & 15) * 8;
    const int lane = tid & 31, warp = tid >> 5;
    const int wm = warp >> 1, wn = warp & 1;
    const int lq = lane >> 2, kq = lane & 3;

    const uint32_t* ap = sm.Arow[ar];
    if (!ap) ap = g_zeroh;

    stage_load(sm, 0, 0, ap, ar, ac, B, ldb, bk, bn);
    cp_commit();
    int st = 0;
    for (int k0p = 0; k0p < Kp; k0p += 16) {
        cp_wait0();
        __syncthreads();
        if (k0p + 16 < Kp) {
            stage_load(sm, st ^ 1, k0p + 16, ap, ar, ac, B, ldb, bk, bn);
            cp_commit();
        }
        stage_compute(sm, st, acc, wm, wn, lq, kq);
        st ^= 1;
    }
}

// ---------------- QKV projection ----------------
__global__ void gemm_qkv_kernel() {
    __shared__ GemmSmem sm;
    int tid = threadIdx.x;
    int nb = blockIdx.x * BN, mb = blockIdx.y * BM;
    const uint32_t* B = (blockIdx.z == 0 ? g_wqh : (blockIdx.z == 1 ? g_wkh : g_wvh)) + nb;
    float* C = (blockIdx.z == 0 ? g_q : (blockIdx.z == 1 ? g_k : g_v));
    if (tid < BM) sm.Arow[tid] = g_xnh + (size_t)(mb + tid) * (H_DIM / 2);
    __syncthreads();
    float acc[2][8][4] = {};
    gemm_run(sm, B, H_DIM, H_DIM / 2, acc, tid);
    int lane = tid & 31, warp = tid >> 5;
    int wm = warp >> 1, wn = warp & 1;
    int lq = lane >> 2, kq = lane & 3;
    #pragma unroll
    for (int mt = 0; mt < 2; mt++) {
        int r0 = mb + wm * 32 + mt * 16 + lq;
        #pragma unroll
        for (int nt = 0; nt < 8; nt++) {
            int c0 = nb + wn * 64 + nt * 8 + 2 * kq;
            C[(size_t)r0 * H_DIM + c0]           = acc[mt][nt][0];
            C[(size_t)r0 * H_DIM + c0 + 1]       = acc[mt][nt][1];
            C[(size_t)(r0 + 8) * H_DIM + c0]     = acc[mt][nt][2];
            C[(size_t)(r0 + 8) * H_DIM + c0 + 1] = acc[mt][nt][3];
        }
    }
}

// ---------------- RoPE ----------------
__global__ void rope_kernel() {
    int gid = blockIdx.x * blockDim.x + threadIdx.x;
    if (gid >= T_TOK * N_HEAD * 32) return;
    int i = gid & 31;
    int n = (gid >> 5) & 15;
    int t = gid >> 9;
    int s = t & (SEQ - 1);
    float inv = __expf(-9.210340371976184f * ((float)i / 32.0f));
    float ang = (float)s * inv;
    float c = cosf(ang), si = sinf(ang);
    size_t base = (size_t)t * H_DIM + n * HEAD_D;
    {
        float x1 = g_q[base + i], x2 = g_q[base + 32 + i];
        g_q[base + i]      = x1 * c - x2 * si;
        g_q[base + 32 + i] = x2 * c + x1 * si;
    }
    {
        float x1 = g_k[base + i], x2 = g_k[base + 32 + i];
        g_k[base + i]      = x1 * c - x2 * si;
        g_k[base + 32 + i] = x2 * c + x1 * si;
    }
}

// ---------------- flash attention (tf32 mma, R16 winner; epilogue -> packed half) ----------------
__global__ void flash_kernel() {
    __shared__ __align__(16) float KP[64][FS];
    __shared__ __align__(16) float Vs[64][FS];
    int qt = blockIdx.x, nh = blockIdx.y, b = blockIdx.z;
    int tid = threadIdx.x, lane = tid & 31, w = tid >> 5;
    int lq = lane >> 2, kq = lane & 3;
    int lrow = tid >> 1, lhalf = tid & 1;

    {
        const float* src = g_q + (size_t)(b * SEQ + qt * 64 + lrow) * H_DIM
                         + nh * HEAD_D + lhalf * 32;
        #pragma unroll
        for (int i = 0; i < 8; i++) {
            float4 v = *(const float4*)(src + i * 4);
            int d = lhalf * 32 + i * 4;
            KP[lrow][d]     = f2tff(v.x * 0.125f);
            KP[lrow][d + 1] = f2tff(v.y * 0.125f);
            KP[lrow][d + 2] = f2tff(v.z * 0.125f);
            KP[lrow][d + 3] = f2tff(v.w * 0.125f);
        }
    }
    __syncthreads();
    uint32_t qf[8][4];
    #pragma unroll
    for (int kc = 0; kc < 8; kc++) {
        qf[kc][0] = __float_as_uint(KP[w * 16 + lq    ][kc * 8 + kq]);
        qf[kc][1] = __float_as_uint(KP[w * 16 + lq + 8][kc * 8 + kq]);
        qf[kc][2] = __float_as_uint(KP[w * 16 + lq    ][kc * 8 + kq + 4]);
        qf[kc][3] = __float_as_uint(KP[w * 16 + lq + 8][kc * 8 + kq + 4]);
    }

    float o[8][4];
    #pragma unroll
    for (int nt = 0; nt < 8; nt++)
        o[nt][0] = o[nt][1] = o[nt][2] = o[nt][3] = 0.f;
    float m0 = -1e30f, m1 = -1e30f, l0 = 0.f, l1 = 0.f;

    for (int kt = 0; kt <= qt; kt++) {
        __syncthreads();
        {
            const float* ks = g_k + (size_t)(b * SEQ + kt * 64 + lrow) * H_DIM
                            + nh * HEAD_D + lhalf * 32;
            const float* vs = g_v + (size_t)(b * SEQ + kt * 64 + lrow) * H_DIM
                            + nh * HEAD_D + lhalf * 32;
            #pragma unroll
            for (int i = 0; i < 8; i++) {
                float4 kv = *(const float4*)(ks + i * 4);
                int d = lhalf * 32 + i * 4;
                KP[d    ][lrow] = f2tff(kv.x);
                KP[d + 1][lrow] = f2tff(kv.y);
                KP[d + 2][lrow] = f2tff(kv.z);
                KP[d + 3][lrow] = f2tff(kv.w);
                float4 vv = *(const float4*)(vs + i * 4);
                Vs[lrow][d]     = f2tff(vv.x);
                Vs[lrow][d + 1] = f2tff(vv.y);
                Vs[lrow][d + 2] = f2tff(vv.z);
                Vs[lrow][d + 3] = f2tff(vv.w);
            }
        }
        __syncthreads();

        float s[8][4];
        #pragma unroll
        for (int nt = 0; nt < 8; nt++)
            s[nt][0] = s[nt][1] = s[nt][2] = s[nt][3] = 0.f;
        #pragma unroll
        for (int kc = 0; kc < 8; kc++) {
            uint32_t bf[8][2];
            #pragma unroll
            for (int nt = 0; nt < 8; nt++) {
                bf[nt][0] = __float_as_uint(KP[kc * 8 + kq    ][nt * 8 + lq]);
                bf[nt][1] = __float_as_uint(KP[kc * 8 + kq + 4][nt * 8 + lq]);
            }
            #pragma unroll
            for (int nt = 0; nt < 8; nt++)
                mma_tf32(s[nt], qf[kc], bf[nt]);
        }

        if (kt == qt) {
            int q0 = w * 16 + lq, q1 = q0 + 8;
            #pragma unroll
            for (int nt = 0; nt < 8; nt++) {
                int c = nt * 8 + 2 * kq;
                if (c     > q0) s[nt][0] = -1e30f;
                if (c + 1 > q0) s[nt][1] = -1e30f;
                if (c     > q1) s[nt][2] = -1e30f;
                if (c + 1 > q1) s[nt][3] = -1e30f;
            }
        }

        float mx0 = -1e30f, mx1 = -1e30f;
        #pragma unroll
        for (int nt = 0; nt < 8; nt++) {
            mx0 = fmaxf(mx0, fmaxf(s[nt][0], s[nt][1]));
            mx1 = fmaxf(mx1, fmaxf(s[nt][2], s[nt][3]));
        }
        mx0 = fmaxf(mx0, __shfl_xor_sync(0xffffffffu, mx0, 1));
        mx0 = fmaxf(mx0, __shfl_xor_sync(0xffffffffu, mx0, 2));
        mx1 = fmaxf(mx1, __shfl_xor_sync(0xffffffffu, mx1, 1));
        mx1 = fmaxf(mx1, __shfl_xor_sync(0xffffffffu, mx1, 2));
        float nm0 = fmaxf(m0, mx0), nm1 = fmaxf(m1, mx1);
        float f0 = __expf(m0 - nm0), f1 = __expf(m1 - nm1);
        m0 = nm0; m1 = nm1;
        float ps0 = 0.f, ps1 = 0.f;
        #pragma unroll
        for (int nt = 0; nt < 8; nt++) {
            s[nt][0] = f2tff(__expf(s[nt][0] - m0)); ps0 += s[nt][0];
            s[nt][1] = f2tff(__expf(s[nt][1] - m0)); ps0 += s[nt][1];
            s[nt][2] = f2tff(__expf(s[nt][2] - m1)); ps1 += s[nt][2];
            s[nt][3] = f2tff(__expf(s[nt][3] - m1)); ps1 += s[nt][3];
        }
        ps0 += __shfl_xor_sync(0xffffffffu, ps0, 1);
        ps0 += __shfl_xor_sync(0xffffffffu, ps0, 2);
        ps1 += __shfl_xor_sync(0xffffffffu, ps1, 1);
        ps1 += __shfl_xor_sync(0xffffffffu, ps1, 2);
        l0 = l0 * f0 + ps0;
        l1 = l1 * f1 + ps1;
        #pragma unroll
        for (int nt = 0; nt < 8; nt++) {
            o[nt][0] *= f0; o[nt][1] *= f0;
            o[nt][2] *= f1; o[nt][3] *= f1;
        }

        __syncthreads();
        {
            float* p0 = &KP[w * 16 + lq    ][2 * kq];
            float* p1 = &KP[w * 16 + lq + 8][2 * kq];
            #pragma unroll
            for (int nt = 0; nt < 8; nt++) {
                p0[nt * 8]     = s[nt][0];
                p0[nt * 8 + 1] = s[nt][1];
                p1[nt * 8]     = s[nt][2];
                p1[nt * 8 + 1] = s[nt][3];
            }
        }
        __syncwarp();

        #pragma unroll
        for (int kc = 0; kc < 8; kc++) {
            uint32_t pa[4];
            pa[0] = __float_as_uint(KP[w * 16 + lq    ][kc * 8 + kq]);
            pa[1] = __float_as_uint(KP[w * 16 + lq + 8][kc * 8 + kq]);
            pa[2] = __float_as_uint(KP[w * 16 + lq    ][kc * 8 + kq + 4]);
            pa[3] = __float_as_uint(KP[w * 16 + lq + 8][kc * 8 + kq + 4]);
            uint32_t bv[8][2];
            #pragma unroll
            for (int nt = 0; nt < 8; nt++) {
                bv[nt][0] = __float_as_uint(Vs[kc * 8 + kq    ][nt * 8 + lq]);
                bv[nt][1] = __float_as_uint(Vs[kc * 8 + kq + 4][nt * 8 + lq]);
            }
            #pragma unroll
            for (int nt = 0; nt < 8; nt++)
                mma_tf32(o[nt], pa, bv[nt]);
        }
    }

    // epilogue: write packed half2 (consecutive pair 2kq,2kq+1 -> one uint32)
    float i0 = 1.f / l0, i1 = 1.f / l1;
    int r0 = b * SEQ + qt * 64 + w * 16 + lq;
    uint32_t* a0 = g_aoh + (size_t)r0 * (H_DIM / 2) + nh * 32 + kq;
    uint32_t* a1 = a0 + (size_t)8 * (H_DIM / 2);
    #pragma unroll
    for (int nt = 0; nt < 8; nt++) {
        a0[nt * 4] = pack_h2(o[nt][0] * i0, o[nt][1] * i0);
        a1[nt * 4] = pack_h2(o[nt][2] * i1, o[nt][3] * i1);
    }
}

// ---------------- WO projection + residual ----------------
__global__ void gemm_wo_kernel(const float* __restrict__ x,
                               float* __restrict__ dout) {
    __shared__ GemmSmem sm;
    int tid = threadIdx.x;
    int nb = blockIdx.x * BN, mb = blockIdx.y * BM;
    if (tid < BM) sm.Arow[tid] = g_aoh + (size_t)(mb + tid) * (H_DIM / 2);
    __syncthreads();
    float acc[2][8][4] = {};
    gemm_run(sm, g_woh + nb, H_DIM, H_DIM / 2, acc, tid);
    int lane = tid & 31, warp = tid >> 5;
    int wm = warp >> 1, wn = warp & 1;
    int lq = lane >> 2, kq = lane & 3;
    #pragma unroll
    for (int mt = 0; mt < 2; mt++) {
        int r0 = mb + wm * 32 + mt * 16 + lq;
        #pragma unroll
        for (int nt = 0; nt < 8; nt++) {
            int c0 = nb + wn * 64 + nt * 8 + 2 * kq;
            #pragma unroll
            for (int h = 0; h < 2; h++) {
                size_t i0 = (size_t)(r0 + h * 8) * H_DIM + c0;
                float v0 = x[i0] + acc[mt][nt][h * 2];
                float v1 = x[i0 + 1] + acc[mt][nt][h * 2 + 1];
                g_x1[i0] = v0; g_x1[i0 + 1] = v1;
                dout[i0] = v0; dout[i0 + 1] = v1;
            }
        }
    }
}

// ---------------- router (fp32 logits) ----------------
__global__ void router_kernel(const float* __restrict__ wr) {
    int warp = (blockIdx.x * blockDim.x + threadIdx.x) >> 5;
    int lane = threadIdx.x & 31;
    if (warp >= T_TOK) return;
    const float* xr = g_xn + (size_t)warp * H_DIM;
    float acc[N_EXP];
    #pragma unroll
    for (int e = 0; e < N_EXP; e++) acc[e] = 0.f;
    for (int h = lane; h < H_DIM; h += 32) {
        float xv = xr[h];
        #pragma unroll
        for (int e = 0; e < N_EXP; e++) acc[e] += xv * wr[h * N_EXP + e];
    }
    #pragma unroll
    for (int e = 0; e < N_EXP; e++)
        #pragma unroll
        for (int o = 16; o > 0; o >>= 1)
            acc[e] += __shfl_down_sync(0xffffffffu, acc[e], o);
    if (lane == 0) {
        float mx = acc[0];
        #pragma unroll
        for (int e = 1; e < N_EXP; e++) mx = fmaxf(mx, acc[e]);
        float p[N_EXP], s = 0.f;
        #pragma unroll
        for (int e = 0; e < N_EXP; e++) { p[e] = expf(acc[e] - mx); s += p[e]; }
        float invs = 1.0f / s;
        #pragma unroll
        for (int e = 0; e < N_EXP; e++) p[e] *= invs;
        int i0 = 0;
        #pragma unroll
        for (int e = 1; e < N_EXP; e++) if (p[e] > p[i0]) i0 = e;
        int i1 = (i0 == 0) ? 1 : 0;
        #pragma unroll
        for (int e = 0; e < N_EXP; e++) if (e != i0 && p[e] > p[i1]) i1 = e;
        float w0 = p[i0], w1 = p[i1];
        float ws = 1.0f / (w0 + w1);
        g_topi[warp * 2] = i0;      g_topi[warp * 2 + 1] = i1;
        g_topw[warp * 2] = w0 * ws; g_topw[warp * 2 + 1] = w1 * ws;
        atomicAdd(&g_cnt[i0], 1);
        atomicAdd(&g_cnt[i1], 1);
        #pragma unroll
        for (int e = 0; e < N_EXP; e++) atomicAdd(&g_psum[e], p[e]);
    }
}

// ---------------- prefix + aux ----------------
__global__ void scan_kernel(float* __restrict__ dout, int write_aux) {
    if (threadIdx.x == 0) {
        int off = 0;
        float aux = 0.f;
        for (int e = 0; e < N_EXP; e++) { g_off[e] = off; off += g_cnt[e]; }
        for (int e = 0; e < N_EXP; e++) {
            float f = (float)g_cnt[e] / (float)(T_TOK * 2);
            float P = g_psum[e] / (float)T_TOK;
            aux += f * P;
        }
        aux *= (float)N_EXP;
        if (write_aux) dout[(size_t)T_TOK * H_DIM] = aux;
    }
}

// ---------------- gather lists ----------------
__global__ void fill_kernel() {
    int gid = blockIdx.x * blockDim.x + threadIdx.x;
    if (gid >= T_TOK * 2) return;
    int t = gid >> 1;
    int e = g_topi[gid];
    int pos = g_off[e] + atomicAdd(&g_fill[e], 1);
    g_slot_tok[pos] = t;
    g_slot_w[pos] = g_topw[gid];
}

// ---------------- MoE GEMM1: h1h = pack(gelu(xn @ w1[e])) ----------------
__global__ void moe_gemm1_kernel() {
    int e = blockIdx.z;
    int cnt = g_cnt[e];
    int mt_ = blockIdx.y;
    if (mt_ * BM >= cnt) return;
    int off = g_off[e];
    __shared__ GemmSmem sm;
    int tid = threadIdx.x;
    if (tid < BM) {
        int rl = mt_ * BM + tid;
        sm.Arow[tid] = (rl < cnt) ? g_xnh + (size_t)g_slot_tok[off + rl] * (H_DIM / 2)
                                  : (const uint32_t*)0;
    }
    __syncthreads();
    int nb = blockIdx.x * BN;
    const uint32_t* B = g_w1h + (size_t)e * (H_DIM / 2) * F_DIM + nb;
    float acc[2][8][4] = {};
    gemm_run(sm, B, F_DIM, H_DIM / 2, acc, tid);
    int lane = tid & 31, warp = tid >> 5;
    int wm = warp >> 1, wn = warp & 1;
    int lq = lane >> 2, kq = lane & 3;
    #pragma unroll
    for (int mt = 0; mt < 2; mt++) {
        #pragma unroll
        for (int h = 0; h < 2; h++) {
            int rl = mt_ * BM + wm * 32 + mt * 16 + lq + h * 8;
            if (rl >= cnt) continue;
            uint32_t* dst = g_h1h + (size_t)(off + rl) * (F_DIM / 2) + nb / 2;
            #pragma unroll
            for (int nt = 0; nt < 8; nt++) {
                int cp = wn * 32 + nt * 4 + kq;   // packed col within tile
                dst[cp] = pack_h2(gelu_tanh(acc[mt][nt][h * 2]),
                                  gelu_tanh(acc[mt][nt][h * 2 + 1]));
            }
        }
    }
}

// ---------------- MoE GEMM2: out += w * (h1 @ w2[e]) ----------------
__global__ void moe_gemm2_kernel(float* __restrict__ dout) {
    int e = blockIdx.z;
    int cnt = g_cnt[e];
    int mt_ = blockIdx.y;
    if (mt_ * BM >= cnt) return;
    int off = g_off[e];
    __shared__ GemmSmem sm;
    int tid = threadIdx.x;
    if (tid < BM) {
        int rl = mt_ * BM + tid;
        sm.Arow[tid] = (rl < cnt) ? g_h1h + (size_t)(off + rl) * (F_DIM / 2)
                                  : (const uint32_t*)0;
    }
    __syncthreads();
    int nb = blockIdx.x * BN;
    const uint32_t* B = g_w2h + (size_t)e * (F_DIM / 2) * H_DIM + nb;
    float acc[2][8][4] = {};
    gemm_run(sm, B, H_DIM, F_DIM / 2, acc, tid);
    int lane = tid & 31, warp = tid >> 5;
    int wm = warp >> 1, wn = warp & 1;
    int lq = lane >> 2, kq = lane & 3;
    #pragma unroll
    for (int mt = 0; mt < 2; mt++) {
        #pragma unroll
        for (int h = 0; h < 2; h++) {
            int rl = mt_ * BM + wm * 32 + mt * 16 + lq + h * 8;
            if (rl >= cnt) continue;
            int tok = g_slot_tok[off + rl];
            float w = g_slot_w[off + rl];
            float* dst = dout + (size_t)tok * H_DIM + nb;
            #pragma unroll
            for (int nt = 0; nt < 8; nt++) {
                int c0 = wn * 64 + nt * 8 + 2 * kq;
                atomicAdd(&dst[c0],     w * acc[mt][nt][h * 2]);
                atomicAdd(&dst[c0 + 1], w * acc[mt][nt][h * 2 + 1]);
            }
        }
    }
}

// ---------------- launch ----------------
extern "C" void kernel_launch(void* const* d_in, const int* in_sizes, int n_in,
                              void* d_out, int out_size) {
    const float* x     = (const float*)d_in[0];
    const float* gattn = (const float*)d_in[1];
    const float* wq    = (const float*)d_in[2];
    const float* wk    = (const float*)d_in[3];
    const float* wv    = (const float*)d_in[4];
    const float* wo    = (const float*)d_in[5];
    const float* gffn  = (const float*)d_in[6];
    const float* wr    = (const float*)d_in[7];
    const float* w1    = (const float*)d_in[8];
    const float* w2    = (const float*)d_in[9];
    float* out = (float*)d_out;
    int write_aux = (out_size > T_TOK * H_DIM) ? 1 : 0;

    // weight conversion (fp32 -> packed half2)
    {
        uint32_t *dq, *dk, *dv, *dw, *d1, *d2;
        cudaGetSymbolAddress((void**)&dq, g_wqh);
        cudaGetSymbolAddress((void**)&dk, g_wkh);
        cudaGetSymbolAddress((void**)&dv, g_wvh);
        cudaGetSymbolAddress((void**)&dw, g_woh);
        cudaGetSymbolAddress((void**)&d1, g_w1h);
        cudaGetSymbolAddress((void**)&d2, g_w2h);
        size_t nsm = (size_t)(H_DIM / 2) * H_DIM;           // 524288
        size_t n1  = (size_t)N_EXP * (H_DIM / 2) * F_DIM;   // 16.8M
        size_t n2  = (size_t)N_EXP * (F_DIM / 2) * H_DIM;   // 16.8M
        int thr = 256;
        cvt_pack_kernel<<<(unsigned)((nsm + thr - 1) / thr), thr>>>(wq, dq, nsm, H_DIM);
        cvt_pack_kernel<<<(unsigned)((nsm + thr - 1) / thr), thr>>>(wk, dk, nsm, H_DIM);
        cvt_pack_kernel<<<(unsigned)((nsm + thr - 1) / thr), thr>>>(wv, dv, nsm, H_DIM);
        cvt_pack_kernel<<<(unsigned)((nsm + thr - 1) / thr), thr>>>(wo, dw, nsm, H_DIM);
        cvt_pack_kernel<<<(unsigned)((n1 + thr - 1) / thr), thr>>>(w1, d1, n1, F_DIM);
        cvt_pack_kernel<<<(unsigned)((n2 + thr - 1) / thr), thr>>>(w2, d2, n2, H_DIM);
    }

    reset_kernel<<<1, 32>>>();

    rmsnorm_kernel<<<T_TOK, 256>>>(x, gattn, 0);
    {
        dim3 g(H_DIM / BN, T_TOK / BM, 3);
        gemm_qkv_kernel<<<g, 256>>>();
    }
    {
        int nthr = T_TOK * N_HEAD * 32;
        rope_kernel<<<(nthr + 255) / 256, 256>>>();
    }
    {
        dim3 g(SEQ / 64, N_HEAD, BATCH);
        flash_kernel<<<g, 128>>>();
    }
    {
        dim3 g(H_DIM / BN, T_TOK / BM);
        gemm_wo_kernel<<<g, 256>>>(x, out);
    }

    rmsnorm_kernel<<<T_TOK, 256>>>(x, gffn, 1);
    router_kernel<<<T_TOK / 4, 128>>>(wr);
    scan_kernel<<<1, 32>>>(out, write_aux);
    fill_kernel<<<(T_TOK * 2 + 255) / 256, 256>>>();
    {
        dim3 g(F_DIM / BN, T_TOK / BM, N_EXP);
        moe_gemm1_kernel<<<g, 256>>>();
    }
    {
        dim3 g(H_DIM / BN, T_TOK / BM, N_EXP);
        moe_gemm2_kernel<<<g, 256>>>(out);
    }
}